// round 17
// baseline (speedup 1.0000x reference)
#include <cuda_runtime.h>

// Mamba-2 SSD forward: b=16, s=1024, h=32, p=64, n=128, block_len=64.
// One CTA per (b,h), 256 threads. 16 chunks sequential; state S[128][64] in smem.
// Phase A: warps 0-3 compute W (C*B^T masked/decayed), warps 4-7 compute
//   Y_off = e*(Ct*S); each thread 8 rows x 4 cols, broadcast operand Ct.
// Phase B: all threads, fused Y = Wt*X + Y_off (4x4) and state update
//   S = E*S + Bd^T*X (8x4) sharing X loads. Packed fma.rn.f32x2 everywhere;
//   row-pairs come free from ulonglong2 loads of the broadcast operand.

#define CL    64
#define NDIM  128
#define HNUM  32
#define SEQ   1024
#define NCHUNK 16
#define TPB   256

typedef unsigned long long u64;

__device__ __forceinline__ u64 pk2(float x, float y) {
    u64 r; asm("mov.b64 %0,{%1,%2};" : "=l"(r) : "f"(x), "f"(y)); return r;
}
__device__ __forceinline__ void upk2(u64 v, float& x, float& y) {
    asm("mov.b64 {%0,%1},%2;" : "=f"(x), "=f"(y) : "l"(v));
}
__device__ __forceinline__ u64 ffma2(u64 a, u64 b, u64 c) {
    u64 d; asm("fma.rn.f32x2 %0,%1,%2,%3;" : "=l"(d) : "l"(a), "l"(b), "l"(c)); return d;
}

// Wt row stagger: +4 words per 8 rows -> conflict-free epilogue stores.
#define WTF(srow) ((srow) * 68 + (((srow) >> 3) << 2))

struct __align__(16) Smem {
    float Ct[NDIM][68];     // C transposed: Ct[n][l]
    float Bt[NDIM][68];     // B transposed: Bt[n][s]
    float S [NDIM][68];     // state: S[n][p]
    float Bd[CL][132];      // B natural, pre-decayed: Bd[l][n]
    float X [CL][68];       // X natural: X[l][p]
    float Wt[CL * 68 + 32]; // W transposed, row-staggered: Wt[s][l]
    float Y2[CL][68];       // Y_off buffer (also scan scratch in prologue)
    float e_[NCHUNK][64];
    float einv_[NCHUNK][64];
    float dl_[NCHUNK][64];
};

__global__ __launch_bounds__(TPB, 1)
void ssd_kernel(const float* __restrict__ gX, const float* __restrict__ gA,
                const float* __restrict__ gB, const float* __restrict__ gC,
                float* __restrict__ gY)
{
    extern __shared__ Smem sm[];
    Smem& s = sm[0];

    const int tid  = threadIdx.x;
    const int lane = tid & 31;
    const int w    = tid >> 5;
    const int bh   = blockIdx.x;
    const int bb   = bh >> 5;
    const int hh   = bh & 31;

    const int xbase = bb * SEQ * (HNUM * 64)   + hh * 64;    // + row*2048
    const int bbase = bb * SEQ * (HNUM * NDIM) + hh * NDIM;  // + row*4096
    const int abase = bb * SEQ * HNUM + hh;

    for (int i = tid; i < NDIM * 68; i += TPB) (&s.S[0][0])[i] = 0.f;

    // ---------- prologue: cumsum + exp factors for ALL 16 chunks ----------
    #pragma unroll
    for (int pass = 0; pass < 4; ++pass) {
        const int cc = (tid >> 6) + pass * 4;
        const int l  = tid & 63;
        float a = gA[abase + (cc * CL + l) * HNUM];
        #pragma unroll
        for (int o = 1; o < 32; o <<= 1) {
            float v = __shfl_up_sync(0xffffffffu, a, o);
            if (lane >= o) a += v;
        }
        s.Y2[cc][l] = a;                 // warp-local inclusive scan (scratch)
        __syncthreads();
        float b31 = s.Y2[cc][31];
        if (l >= 32) a += b31;
        float last = s.Y2[cc][63] + b31;
        s.e_[cc][l]    = expf(a);
        s.einv_[cc][l] = expf(-a);
        s.dl_[cc][l]   = expf(last - a);
        __syncthreads();
    }

    // Phase A mapping: warp = 4 row-groups x 8 col-groups
    const int rgA  = ((w & 1) << 2) | (lane >> 3);   // 0..7
    const int cgA  = ((w >> 1) << 3) | (lane & 7);   // 0..31
    const int l0A  = rgA * 8;
    const int sp0A = (cgA & 15) * 4;
    const bool isW = (cgA < 16);

    // Phase B mapping: warp = 4 g-groups x 8 p-groups
    const int gB_ = ((w & 3) << 2) | (lane >> 3);    // 0..15
    const int pgB = ((w >> 2) << 3) | (lane & 7);    // 0..15
    const int l0B = gB_ * 4;
    const int p0B = pgB * 4;
    const int n0B = gB_ * 8;

    for (int c = 0; c < NCHUNK; ++c) {
        const int srow0 = c * CL;

        // ---------- load chunk ----------
        #pragma unroll
        for (int k = 0; k < 4; ++k) {           // X: 1024 float4
            int idx = k * TPB + tid;
            int l = idx >> 4, c4 = (idx & 15) * 4;
            *(float4*)&s.X[l][c4] =
                *(const float4*)(gX + xbase + (srow0 + l) * 2048 + c4);
        }
        #pragma unroll
        for (int k = 0; k < 8; ++k) {           // B -> Bt (transpose scatter)
            int idx = k * TPB + tid;
            int l = idx & 63, nn = (idx >> 6) * 4;
            float4 v = *(const float4*)(gB + bbase + (srow0 + l) * 4096 + nn);
            s.Bt[nn + 0][l] = v.x; s.Bt[nn + 1][l] = v.y;
            s.Bt[nn + 2][l] = v.z; s.Bt[nn + 3][l] = v.w;
        }
        #pragma unroll
        for (int k = 0; k < 8; ++k) {           // B -> Bd (natural, decayed; coalesced)
            int idx = k * TPB + tid;
            int l = idx >> 5, c4 = (idx & 31) * 4;
            float4 v = *(const float4*)(gB + bbase + (srow0 + l) * 4096 + c4);
            float d = s.dl_[c][l];
            *(float4*)&s.Bd[l][c4] = make_float4(v.x * d, v.y * d, v.z * d, v.w * d);
        }
        #pragma unroll
        for (int k = 0; k < 8; ++k) {           // C -> Ct (transpose scatter)
            int idx = k * TPB + tid;
            int l = idx & 63, nn = (idx >> 6) * 4;
            float4 v = *(const float4*)(gC + bbase + (srow0 + l) * 4096 + nn);
            s.Ct[nn + 0][l] = v.x; s.Ct[nn + 1][l] = v.y;
            s.Ct[nn + 2][l] = v.z; s.Ct[nn + 3][l] = v.w;
        }
        __syncthreads();

        // ================= PHASE A =================
        {
            u64 acc[4][4] = {};     // [row-pair][col]
            const float* src = isW ? &s.Bt[0][sp0A] : &s.S[0][sp0A];
            if (!isW || (l0A + 7 >= sp0A)) {    // triangular skip (W only)
                #pragma unroll 4
                for (int k = 0; k < NDIM; ++k) {
                    ulonglong2 a01 = *(const ulonglong2*)&s.Ct[k][l0A];
                    ulonglong2 a23 = *(const ulonglong2*)&s.Ct[k][l0A + 4];
                    float4 bv = *(const float4*)(src + k * 68);
                    u64 ap[4] = {a01.x, a01.y, a23.x, a23.y};
                    u64 bd[4] = {pk2(bv.x, bv.x), pk2(bv.y, bv.y),
                                 pk2(bv.z, bv.z), pk2(bv.w, bv.w)};
                    #pragma unroll
                    for (int i2 = 0; i2 < 4; ++i2)
                        #pragma unroll
                        for (int j = 0; j < 4; ++j)
                            acc[i2][j] = ffma2(ap[i2], bd[j], acc[i2][j]);
                }
            }
            float v[8][4];
            #pragma unroll
            for (int i2 = 0; i2 < 4; ++i2)
                #pragma unroll
                for (int j = 0; j < 4; ++j)
                    upk2(acc[i2][j], v[2 * i2][j], v[2 * i2 + 1][j]);
            float el[8];
            #pragma unroll
            for (int i = 0; i < 8; ++i) el[i] = s.e_[c][l0A + i];

            if (isW) {
                #pragma unroll
                for (int j = 0; j < 4; ++j) {
                    float ei = s.einv_[c][sp0A + j];
                    float m[8];
                    #pragma unroll
                    for (int i = 0; i < 8; ++i)
                        m[i] = (l0A + i >= sp0A + j) ? v[i][j] * el[i] * ei : 0.f;
                    float* wp = &s.Wt[WTF(sp0A + j) + l0A];
                    *(float4*)(wp)     = make_float4(m[0], m[1], m[2], m[3]);
                    *(float4*)(wp + 4) = make_float4(m[4], m[5], m[6], m[7]);
                }
            } else {
                #pragma unroll
                for (int i = 0; i < 8; ++i)
                    *(float4*)&s.Y2[l0A + i][sp0A] =
                        make_float4(el[i] * v[i][0], el[i] * v[i][1],
                                    el[i] * v[i][2], el[i] * v[i][3]);
            }
        }
        __syncthreads();

        // ================= PHASE B =================
        {
            // init accO from Y_off
            u64 accO[2][4];
            {
                float4 y0 = *(const float4*)&s.Y2[l0B + 0][p0B];
                float4 y1 = *(const float4*)&s.Y2[l0B + 1][p0B];
                float4 y2 = *(const float4*)&s.Y2[l0B + 2][p0B];
                float4 y3 = *(const float4*)&s.Y2[l0B + 3][p0B];
                accO[0][0] = pk2(y0.x, y1.x); accO[0][1] = pk2(y0.y, y1.y);
                accO[0][2] = pk2(y0.z, y1.z); accO[0][3] = pk2(y0.w, y1.w);
                accO[1][0] = pk2(y2.x, y3.x); accO[1][1] = pk2(y2.y, y3.y);
                accO[1][2] = pk2(y2.z, y3.z); accO[1][3] = pk2(y2.w, y3.w);
            }
            const float E = s.e_[c][CL - 1];
            u64 accS[4][4];
            #pragma unroll
            for (int r2 = 0; r2 < 4; ++r2) {
                float4 s0v = *(const float4*)&s.S[n0B + 2 * r2][p0B];
                float4 s1v = *(const float4*)&s.S[n0B + 2 * r2 + 1][p0B];
                accS[r2][0] = pk2(s0v.x * E, s1v.x * E);
                accS[r2][1] = pk2(s0v.y * E, s1v.y * E);
                accS[r2][2] = pk2(s0v.z * E, s1v.z * E);
                accS[r2][3] = pk2(s0v.w * E, s1v.w * E);
            }
            #pragma unroll 4
            for (int k = 0; k < CL; ++k) {
                float4 xv = *(const float4*)&s.X[k][p0B];
                u64 xd[4] = {pk2(xv.x, xv.x), pk2(xv.y, xv.y),
                             pk2(xv.z, xv.z), pk2(xv.w, xv.w)};
                ulonglong2 wv = *(const ulonglong2*)&s.Wt[WTF(k) + l0B];
                #pragma unroll
                for (int j = 0; j < 4; ++j) {
                    accO[0][j] = ffma2(wv.x, xd[j], accO[0][j]);
                    accO[1][j] = ffma2(wv.y, xd[j], accO[1][j]);
                }
                ulonglong2 g0 = *(const ulonglong2*)&s.Bd[k][n0B];
                ulonglong2 g1 = *(const ulonglong2*)&s.Bd[k][n0B + 4];
                u64 bp[4] = {g0.x, g0.y, g1.x, g1.y};
                #pragma unroll
                for (int r2 = 0; r2 < 4; ++r2)
                    #pragma unroll
                    for (int j = 0; j < 4; ++j)
                        accS[r2][j] = ffma2(bp[r2], xd[j], accS[r2][j]);
            }
            // store Y
            float yv[4][4];
            #pragma unroll
            for (int i2 = 0; i2 < 2; ++i2)
                #pragma unroll
                for (int j = 0; j < 4; ++j)
                    upk2(accO[i2][j], yv[2 * i2][j], yv[2 * i2 + 1][j]);
            #pragma unroll
            for (int i = 0; i < 4; ++i)
                *(float4*)(gY + xbase + (srow0 + l0B + i) * 2048 + p0B) =
                    make_float4(yv[i][0], yv[i][1], yv[i][2], yv[i][3]);
            // store S
            float sv[8][4];
            #pragma unroll
            for (int r2 = 0; r2 < 4; ++r2)
                #pragma unroll
                for (int j = 0; j < 4; ++j)
                    upk2(accS[r2][j], sv[2 * r2][j], sv[2 * r2 + 1][j]);
            #pragma unroll
            for (int r = 0; r < 8; ++r)
                *(float4*)&s.S[n0B + r][p0B] =
                    make_float4(sv[r][0], sv[r][1], sv[r][2], sv[r][3]);
        }
        __syncthreads();   // protect all buffers before next chunk's loads
    }
}

extern "C" void kernel_launch(void* const* d_in, const int* in_sizes, int n_in,
                              void* d_out, int out_size)
{
    const float* X = (const float*)d_in[0];
    const float* A = (const float*)d_in[1];
    const float* B = (const float*)d_in[2];
    const float* C = (const float*)d_in[3];
    float*       Y = (float*)d_out;

    cudaFuncSetAttribute(ssd_kernel,
                         cudaFuncAttributeMaxDynamicSharedMemorySize,
                         (int)sizeof(Smem));
    ssd_kernel<<<16 * HNUM, TPB, sizeof(Smem)>>>(X, A, B, C, Y);
}